// round 2
// baseline (speedup 1.0000x reference)
#include <cuda_runtime.h>
#include <math.h>

#define TT 4096
#define HH 2048
#define EE 32
#define II 1024
#define TOPK 8
#define MAXPAIRS (TT * TOPK)

// ---------------- device scratch (allocation-free, BSS) ----------------
__device__ int   g_count[EE];
__device__ int   g_cursor[EE];
__device__ int   g_off[EE + 1];
__device__ int   g_topk_e[MAXPAIRS];
__device__ float g_topk_w[MAXPAIRS];
__device__ int   g_pair_tok[MAXPAIRS];
__device__ float g_pair_w[MAXPAIRS];
__device__ float g_h[(size_t)MAXPAIRS * II];   // 134 MB intermediate

// ---------------- init: zero counters each replay ----------------
__global__ void init_kernel() {
    int i = threadIdx.x;
    if (i < EE) { g_count[i] = 0; g_cursor[i] = 0; }
}

// ---------------- router: logits + softmax + top8 + renorm ----------------
__global__ void router_kernel(const float* __restrict__ x,
                              const float* __restrict__ gate_w,
                              float* __restrict__ out, int write_ids) {
    int t = blockIdx.x;
    int tid = threadIdx.x;           // 128 threads
    int e = tid >> 2, p = tid & 3;   // 32 experts x 4 partials
    const float* xr = x + (size_t)t * HH;
    float s = 0.f;
    for (int h = p; h < HH; h += 4)
        s += xr[h] * gate_w[(size_t)h * EE + e];
    __shared__ float part[EE][4];
    part[e][p] = s;
    __syncthreads();
    __shared__ float sc[EE];
    if (tid < EE)
        sc[tid] = part[tid][0] + part[tid][1] + part[tid][2] + part[tid][3];
    __syncthreads();
    if (tid == 0) {
        float mx = sc[0];
        #pragma unroll
        for (int i = 1; i < EE; i++) mx = fmaxf(mx, sc[i]);
        float sum = 0.f;
        for (int i = 0; i < EE; i++) { sc[i] = expf(sc[i] - mx); sum += sc[i]; }
        float inv = 1.f / sum;
        for (int i = 0; i < EE; i++) sc[i] *= inv;
        // greedy top-8, ties -> lowest index (matches jax.lax.top_k)
        int ids[TOPK]; float ws[TOPK];
        unsigned used = 0u; float wsum = 0.f;
        for (int k = 0; k < TOPK; k++) {
            int best = 0; float bv = -1.f;
            for (int i = 0; i < EE; i++) {
                if (!((used >> i) & 1u) && sc[i] > bv) { bv = sc[i]; best = i; }
            }
            used |= (1u << best); ids[k] = best; ws[k] = bv; wsum += bv;
        }
        float invw = 1.f / wsum;
        for (int k = 0; k < TOPK; k++) {
            g_topk_e[t * TOPK + k] = ids[k];
            g_topk_w[t * TOPK + k] = ws[k] * invw;
            atomicAdd(&g_count[ids[k]], 1);
            if (write_ids)
                out[(size_t)TT * HH + (size_t)t * TOPK + k] = (float)ids[k];
        }
    }
}

// ---------------- prefix sum of counts ----------------
__global__ void prefix_kernel() {
    if (threadIdx.x == 0) {
        int acc = 0;
        for (int e = 0; e < EE; e++) { g_off[e] = acc; acc += g_count[e]; }
        g_off[EE] = acc;
    }
}

// ---------------- scatter token/weight into per-expert segments ----------------
__global__ void scatter_kernel() {
    int idx = blockIdx.x * blockDim.x + threadIdx.x;
    if (idx >= TT * TOPK) return;
    int e = g_topk_e[idx];
    int pos = atomicAdd(&g_cursor[e], 1);
    int slot = g_off[e] + pos;
    g_pair_tok[slot] = idx / TOPK;
    g_pair_w[slot]   = g_topk_w[idx];
}

// ---------------- GEMM1: h = silu(X@Wg) * (X@Wu), gathered rows ----------------
// BM=128, BN=64, BK=16, 256 threads, 8x4 microtile, dual accumulators,
// register-staged prefetch of the next K-tile.
__global__ __launch_bounds__(256, 2) void moe_gemm1(
    const float* __restrict__ x,
    const float* __restrict__ w_gate,
    const float* __restrict__ w_up) {
    const int e   = blockIdx.z;
    const int cnt = g_count[e];
    const int m0  = blockIdx.y * 128;
    if (m0 >= cnt) return;
    const int n0  = blockIdx.x * 64;
    const int off = g_off[e];

    __shared__ float As[16][128];
    __shared__ float Bg[16][64];
    __shared__ float Bu[16][64];
    __shared__ int   toks[128];

    const int tid = threadIdx.x;
    for (int r = tid; r < 128; r += 256)
        toks[r] = (m0 + r < cnt) ? g_pair_tok[off + m0 + r] : -1;
    __syncthreads();

    const float* Wg = w_gate + (size_t)e * HH * II;
    const float* Wu = w_up   + (size_t)e * HH * II;

    const int arow = tid >> 1,  acol = (tid & 1) * 8;   // A tile 128x16
    const int brow = tid >> 4,  bcol = (tid & 15) * 4;  // B tile 16x64
    const int ty = tid >> 4,    tx = tid & 15;

    float cg[8][4], cu[8][4];
    #pragma unroll
    for (int i = 0; i < 8; i++)
        #pragma unroll
        for (int j = 0; j < 4; j++) { cg[i][j] = 0.f; cu[i][j] = 0.f; }

    const int tokA = toks[arow];
    const float* arp = x + (size_t)(tokA < 0 ? 0 : tokA) * HH;

    // prefetch tile 0
    float4 a0, a1, bgv, buv;
    if (tokA >= 0) {
        a0 = *(const float4*)(arp + acol);
        a1 = *(const float4*)(arp + acol + 4);
    } else { a0 = make_float4(0.f,0.f,0.f,0.f); a1 = a0; }
    bgv = *(const float4*)(Wg + (size_t)brow * II + n0 + bcol);
    buv = *(const float4*)(Wu + (size_t)brow * II + n0 + bcol);

    for (int k0 = 0; k0 < HH; k0 += 16) {
        As[acol + 0][arow] = a0.x; As[acol + 1][arow] = a0.y;
        As[acol + 2][arow] = a0.z; As[acol + 3][arow] = a0.w;
        As[acol + 4][arow] = a1.x; As[acol + 5][arow] = a1.y;
        As[acol + 6][arow] = a1.z; As[acol + 7][arow] = a1.w;
        *(float4*)&Bg[brow][bcol] = bgv;
        *(float4*)&Bu[brow][bcol] = buv;
        __syncthreads();
        // issue next tile's global loads early (latency overlap with FMAs)
        int kn = k0 + 16;
        if (kn < HH) {
            if (tokA >= 0) {
                a0 = *(const float4*)(arp + kn + acol);
                a1 = *(const float4*)(arp + kn + acol + 4);
            }
            bgv = *(const float4*)(Wg + (size_t)(kn + brow) * II + n0 + bcol);
            buv = *(const float4*)(Wu + (size_t)(kn + brow) * II + n0 + bcol);
        }
        #pragma unroll
        for (int kk = 0; kk < 16; kk++) {
            float a[8], bg[4], bu[4];
            *(float4*)&a[0] = *(const float4*)&As[kk][ty * 8];
            *(float4*)&a[4] = *(const float4*)&As[kk][ty * 8 + 4];
            *(float4*)&bg[0] = *(const float4*)&Bg[kk][tx * 4];
            *(float4*)&bu[0] = *(const float4*)&Bu[kk][tx * 4];
            #pragma unroll
            for (int i = 0; i < 8; i++)
                #pragma unroll
                for (int j = 0; j < 4; j++) {
                    cg[i][j] = fmaf(a[i], bg[j], cg[i][j]);
                    cu[i][j] = fmaf(a[i], bu[j], cu[i][j]);
                }
        }
        __syncthreads();
    }
    #pragma unroll
    for (int i = 0; i < 8; i++) {
        int m = m0 + ty * 8 + i;
        if (m < cnt) {
            float4 hv;
            float g;
            g = cg[i][0]; hv.x = g / (1.f + __expf(-g)) * cu[i][0];
            g = cg[i][1]; hv.y = g / (1.f + __expf(-g)) * cu[i][1];
            g = cg[i][2]; hv.z = g / (1.f + __expf(-g)) * cu[i][2];
            g = cg[i][3]; hv.w = g / (1.f + __expf(-g)) * cu[i][3];
            *(float4*)(g_h + (size_t)(off + m) * II + n0 + tx * 4) = hv;
        }
    }
}

// ---------------- GEMM2: out += w * (h @ Wd), scatter via atomicAdd ----------------
// BM=128, BN=128, BK=16, 256 threads, 8x8 microtile, register-staged prefetch.
__global__ __launch_bounds__(256, 2) void moe_gemm2(
    const float* __restrict__ w_down, float* __restrict__ out) {
    const int e   = blockIdx.z;
    const int cnt = g_count[e];
    const int m0  = blockIdx.y * 128;
    if (m0 >= cnt) return;
    const int n0  = blockIdx.x * 128;
    const int off = g_off[e];

    __shared__ float As[16][128];
    __shared__ float Bs[16][128];
    __shared__ int   toks[128];
    __shared__ float wts[128];

    const int tid = threadIdx.x;
    for (int r = tid; r < 128; r += 256) {
        int valid = (m0 + r < cnt);
        toks[r] = valid ? g_pair_tok[off + m0 + r] : -1;
        wts[r]  = valid ? g_pair_w[off + m0 + r]   : 0.f;
    }
    __syncthreads();

    const float* Wd = w_down + (size_t)e * II * HH;

    const int arow = tid >> 1,  acol = (tid & 1) * 8;   // A tile 128x16
    const int brow = tid >> 4,  bcol = (tid & 15) * 8;  // B tile 16x128
    const int ty = tid >> 4,    tx = tid & 15;

    const int avalid = (m0 + arow < cnt);
    const float* aptr = g_h + (size_t)(avalid ? (off + m0 + arow) : 0) * II;

    float c[8][8];
    #pragma unroll
    for (int i = 0; i < 8; i++)
        #pragma unroll
        for (int j = 0; j < 8; j++) c[i][j] = 0.f;

    float4 a0, a1, b0, b1;
    if (avalid) {
        a0 = *(const float4*)(aptr + acol);
        a1 = *(const float4*)(aptr + acol + 4);
    } else { a0 = make_float4(0.f,0.f,0.f,0.f); a1 = a0; }
    b0 = *(const float4*)(Wd + (size_t)brow * HH + n0 + bcol);
    b1 = *(const float4*)(Wd + (size_t)brow * HH + n0 + bcol + 4);

    for (int k0 = 0; k0 < II; k0 += 16) {
        As[acol + 0][arow] = a0.x; As[acol + 1][arow] = a0.y;
        As[acol + 2][arow] = a0.z; As[acol + 3][arow] = a0.w;
        As[acol + 4][arow] = a1.x; As[acol + 5][arow] = a1.y;
        As[acol + 6][arow] = a1.z; As[acol + 7][arow] = a1.w;
        *(float4*)&Bs[brow][bcol]     = b0;
        *(float4*)&Bs[brow][bcol + 4] = b1;
        __syncthreads();
        int kn = k0 + 16;
        if (kn < II) {
            if (avalid) {
                a0 = *(const float4*)(aptr + kn + acol);
                a1 = *(const float4*)(aptr + kn + acol + 4);
            }
            b0 = *(const float4*)(Wd + (size_t)(kn + brow) * HH + n0 + bcol);
            b1 = *(const float4*)(Wd + (size_t)(kn + brow) * HH + n0 + bcol + 4);
        }
        #pragma unroll
        for (int kk = 0; kk < 16; kk++) {
            float a[8], b[8];
            *(float4*)&a[0] = *(const float4*)&As[kk][ty * 8];
            *(float4*)&a[4] = *(const float4*)&As[kk][ty * 8 + 4];
            *(float4*)&b[0] = *(const float4*)&Bs[kk][tx * 8];
            *(float4*)&b[4] = *(const float4*)&Bs[kk][tx * 8 + 4];
            #pragma unroll
            for (int i = 0; i < 8; i++)
                #pragma unroll
                for (int j = 0; j < 8; j++)
                    c[i][j] = fmaf(a[i], b[j], c[i][j]);
        }
        __syncthreads();
    }
    #pragma unroll
    for (int i = 0; i < 8; i++) {
        int m = m0 + ty * 8 + i;
        if (m < cnt) {
            int tok = toks[ty * 8 + i];
            float w = wts[ty * 8 + i];
            float* dst = out + (size_t)tok * HH + n0 + tx * 8;
            #pragma unroll
            for (int j = 0; j < 8; j++)
                atomicAdd(dst + j, w * c[i][j]);
        }
    }
}

// ---------------- launch ----------------
extern "C" void kernel_launch(void* const* d_in, const int* in_sizes, int n_in,
                              void* d_out, int out_size) {
    const float* x      = (const float*)d_in[0];
    const float* gate_w = (const float*)d_in[1];
    const float* w_gate = (const float*)d_in[2];
    const float* w_up   = (const float*)d_in[3];
    const float* w_down = (const float*)d_in[4];
    float* out = (float*)d_out;

    cudaMemsetAsync(d_out, 0, (size_t)out_size * sizeof(float), 0);
    init_kernel<<<1, 32>>>();

    int write_ids = (out_size >= TT * HH + TT * TOPK) ? 1 : 0;
    router_kernel<<<TT, 128>>>(x, gate_w, out, write_ids);
    prefix_kernel<<<1, 32>>>();
    scatter_kernel<<<(TT * TOPK + 255) / 256, 256>>>();

    dim3 g1(II / 64, TT / 128, EE);
    moe_gemm1<<<g1, 256>>>(x, w_gate, w_up);

    dim3 g2(HH / 128, TT / 128, EE);
    moe_gemm2<<<g2, 256>>>(w_down, out);
}

// round 4
// speedup vs baseline: 1.9205x; 1.9205x over previous
#include <cuda_runtime.h>
#include <cstdint>
#include <math.h>

#define TT 4096
#define HH 2048
#define EE 32
#define II 1024
#define TOPK 8
#define MAXPAIRS (TT * TOPK)

// ---------------- device scratch (allocation-free BSS) ----------------
__device__ int   g_count[EE];
__device__ int   g_cursor[EE];
__device__ int   g_off[EE + 1];
__device__ int   g_topk_e[MAXPAIRS];
__device__ float g_topk_w[MAXPAIRS];
__device__ int   g_pair_tok[MAXPAIRS];
__device__ float g_pair_w[MAXPAIRS];
__device__ float g_h[(size_t)MAXPAIRS * II];   // 134 MB intermediate

// ---------------- helpers ----------------
__device__ __forceinline__ float tf32r(float v) {
    uint32_t u;
    asm("cvt.rna.tf32.f32 %0, %1;" : "=r"(u) : "f"(v));
    return __uint_as_float(u);
}
__device__ __forceinline__ float4 tf32r4(float4 v) {
    v.x = tf32r(v.x); v.y = tf32r(v.y); v.z = tf32r(v.z); v.w = tf32r(v.w);
    return v;
}
__device__ __forceinline__ void mma_t32(float* c, const uint32_t* a, const uint32_t* b) {
    asm volatile(
        "mma.sync.aligned.m16n8k8.row.col.f32.tf32.tf32.f32 "
        "{%0,%1,%2,%3}, {%4,%5,%6,%7}, {%8,%9}, {%0,%1,%2,%3};"
        : "+f"(c[0]), "+f"(c[1]), "+f"(c[2]), "+f"(c[3])
        : "r"(a[0]), "r"(a[1]), "r"(a[2]), "r"(a[3]), "r"(b[0]), "r"(b[1]));
}

// ---------------- init ----------------
__global__ void init_kernel() {
    int i = threadIdx.x;
    if (i < EE) { g_count[i] = 0; g_cursor[i] = 0; }
}

// ---------------- router ----------------
__global__ void router_kernel(const float* __restrict__ x,
                              const float* __restrict__ gate_w,
                              float* __restrict__ out, int write_ids) {
    int t = blockIdx.x;
    int tid = threadIdx.x;           // 128
    int e = tid >> 2, p = tid & 3;
    const float* xr = x + (size_t)t * HH;
    float s = 0.f;
    for (int h = p; h < HH; h += 4)
        s += xr[h] * gate_w[(size_t)h * EE + e];
    __shared__ float part[EE][4];
    part[e][p] = s;
    __syncthreads();
    __shared__ float sc[EE];
    if (tid < EE)
        sc[tid] = part[tid][0] + part[tid][1] + part[tid][2] + part[tid][3];
    __syncthreads();
    if (tid == 0) {
        float mx = sc[0];
        #pragma unroll
        for (int i = 1; i < EE; i++) mx = fmaxf(mx, sc[i]);
        float sum = 0.f;
        for (int i = 0; i < EE; i++) { sc[i] = expf(sc[i] - mx); sum += sc[i]; }
        float inv = 1.f / sum;
        for (int i = 0; i < EE; i++) sc[i] *= inv;
        int ids[TOPK]; float ws[TOPK];
        unsigned used = 0u; float wsum = 0.f;
        for (int k = 0; k < TOPK; k++) {
            int best = 0; float bv = -1.f;
            for (int i = 0; i < EE; i++)
                if (!((used >> i) & 1u) && sc[i] > bv) { bv = sc[i]; best = i; }
            used |= (1u << best); ids[k] = best; ws[k] = bv; wsum += bv;
        }
        float invw = 1.f / wsum;
        for (int k = 0; k < TOPK; k++) {
            g_topk_e[t * TOPK + k] = ids[k];
            g_topk_w[t * TOPK + k] = ws[k] * invw;
            atomicAdd(&g_count[ids[k]], 1);
            if (write_ids)
                out[(size_t)TT * HH + (size_t)t * TOPK + k] = (float)ids[k];
        }
    }
}

__global__ void prefix_kernel() {
    if (threadIdx.x == 0) {
        int acc = 0;
        for (int e = 0; e < EE; e++) { g_off[e] = acc; acc += g_count[e]; }
        g_off[EE] = acc;
    }
}

__global__ void scatter_kernel() {
    int idx = blockIdx.x * blockDim.x + threadIdx.x;
    if (idx >= TT * TOPK) return;
    int e = g_topk_e[idx];
    int pos = atomicAdd(&g_cursor[e], 1);
    int slot = g_off[e] + pos;
    g_pair_tok[slot] = idx / TOPK;
    g_pair_w[slot]   = g_topk_w[idx];
}

// ---------------- GEMM1 (tf32 mma.sync): h = silu(X@Wg) * (X@Wu) ----------------
// BM=128, BN=64, BK=32, 256 threads (8 warps, 4x2), warp tile 32x32 dual.
#define APAD 36
#define BPAD 72
__global__ __launch_bounds__(256) void moe_gemm1(
    const float* __restrict__ x,
    const float* __restrict__ w_gate,
    const float* __restrict__ w_up) {
    const int e   = blockIdx.z;
    const int cnt = g_count[e];
    const int m0  = blockIdx.x * 128;
    if (m0 >= cnt) return;
    const int n0  = blockIdx.y * 64;
    const int off = g_off[e];

    __shared__ float As[128 * APAD];
    __shared__ float Bg[32 * BPAD];
    __shared__ float Bu[32 * BPAD];
    __shared__ int   toks[128];

    const int tid = threadIdx.x;
    for (int r = tid; r < 128; r += 256)
        toks[r] = (m0 + r < cnt) ? g_pair_tok[off + m0 + r] : 0;
    __syncthreads();

    const int lane = tid & 31, wid = tid >> 5;
    const int gid = lane >> 2, tig = lane & 3;
    const int wm = (wid >> 1) * 32, wn = (wid & 1) * 32;

    // global->smem mappings
    const int arow = tid >> 1, aq = (tid & 1) * 16;                  // 16 floats each
    const float* aptr = x + (size_t)toks[arow] * HH + aq;
    const int brow = tid >> 3, bq = (tid & 7) * 8;                   // 8 floats each
    const float* bgp = w_gate + (size_t)e * HH * II + (size_t)brow * II + n0 + bq;
    const float* bup = w_up   + (size_t)e * HH * II + (size_t)brow * II + n0 + bq;

    float cg[2][4][4], cu[2][4][4];
    #pragma unroll
    for (int i = 0; i < 2; i++)
        #pragma unroll
        for (int j = 0; j < 4; j++)
            #pragma unroll
            for (int q = 0; q < 4; q++) { cg[i][j][q] = 0.f; cu[i][j][q] = 0.f; }

    float4 pa[4], pg[2], pu[2];
    #pragma unroll
    for (int v = 0; v < 4; v++) pa[v] = *(const float4*)(aptr + v * 4);
    #pragma unroll
    for (int v = 0; v < 2; v++) {
        pg[v] = *(const float4*)(bgp + v * 4);
        pu[v] = *(const float4*)(bup + v * 4);
    }

    for (int kt = 0; kt < HH / 32; kt++) {
        #pragma unroll
        for (int v = 0; v < 4; v++)
            *(float4*)&As[arow * APAD + aq + v * 4] = tf32r4(pa[v]);
        #pragma unroll
        for (int v = 0; v < 2; v++) {
            *(float4*)&Bg[brow * BPAD + bq + v * 4] = tf32r4(pg[v]);
            *(float4*)&Bu[brow * BPAD + bq + v * 4] = tf32r4(pu[v]);
        }
        __syncthreads();
        if (kt + 1 < HH / 32) {
            const int kn = (kt + 1) * 32;
            #pragma unroll
            for (int v = 0; v < 4; v++) pa[v] = *(const float4*)(aptr + kn + v * 4);
            #pragma unroll
            for (int v = 0; v < 2; v++) {
                pg[v] = *(const float4*)(bgp + (size_t)kn * II + v * 4);
                pu[v] = *(const float4*)(bup + (size_t)kn * II + v * 4);
            }
        }
        #pragma unroll
        for (int ks = 0; ks < 4; ks++) {
            const int kb = ks * 8;
            uint32_t af[2][4], bgf[4][2], buf_[4][2];
            #pragma unroll
            for (int mi = 0; mi < 2; mi++) {
                const int r = wm + mi * 16 + gid;
                af[mi][0] = __float_as_uint(As[r * APAD + kb + tig]);
                af[mi][1] = __float_as_uint(As[(r + 8) * APAD + kb + tig]);
                af[mi][2] = __float_as_uint(As[r * APAD + kb + tig + 4]);
                af[mi][3] = __float_as_uint(As[(r + 8) * APAD + kb + tig + 4]);
            }
            #pragma unroll
            for (int ni = 0; ni < 4; ni++) {
                const int c = wn + ni * 8 + gid;
                bgf[ni][0] = __float_as_uint(Bg[(kb + tig) * BPAD + c]);
                bgf[ni][1] = __float_as_uint(Bg[(kb + tig + 4) * BPAD + c]);
                buf_[ni][0] = __float_as_uint(Bu[(kb + tig) * BPAD + c]);
                buf_[ni][1] = __float_as_uint(Bu[(kb + tig + 4) * BPAD + c]);
            }
            #pragma unroll
            for (int mi = 0; mi < 2; mi++)
                #pragma unroll
                for (int ni = 0; ni < 4; ni++) {
                    mma_t32(cg[mi][ni], af[mi], bgf[ni]);
                    mma_t32(cu[mi][ni], af[mi], buf_[ni]);
                }
        }
        __syncthreads();
    }
    // epilogue: silu(g)*u -> g_h
    #pragma unroll
    for (int mi = 0; mi < 2; mi++) {
        #pragma unroll
        for (int half = 0; half < 2; half++) {
            const int m = m0 + wm + mi * 16 + gid + half * 8;
            if (m < cnt) {
                float* hrow = g_h + (size_t)(off + m) * II + n0 + wn;
                #pragma unroll
                for (int ni = 0; ni < 4; ni++) {
                    float g0 = cg[mi][ni][half * 2], g1 = cg[mi][ni][half * 2 + 1];
                    float u0 = cu[mi][ni][half * 2], u1 = cu[mi][ni][half * 2 + 1];
                    float2 o;
                    o.x = g0 / (1.f + __expf(-g0)) * u0;
                    o.y = g1 / (1.f + __expf(-g1)) * u1;
                    *(float2*)(hrow + ni * 8 + tig * 2) = o;
                }
            }
        }
    }
}

// ---------------- GEMM2 (tf32 mma.sync): out += w * (h @ Wd) ----------------
// BM=128, BN=128, BK=32, 8 warps (2x4), warp tile 64x32, atomicAdd epilogue.
#define B2PAD 136
__global__ __launch_bounds__(256) void moe_gemm2(
    const float* __restrict__ w_down, float* __restrict__ out) {
    const int e   = blockIdx.z;
    const int cnt = g_count[e];
    const int m0  = blockIdx.x * 128;
    if (m0 >= cnt) return;
    const int n0  = blockIdx.y * 128;
    const int off = g_off[e];

    __shared__ float As[128 * APAD];
    __shared__ float Bs[32 * B2PAD];
    __shared__ int   toks[128];
    __shared__ float wts[128];

    const int tid = threadIdx.x;
    for (int r = tid; r < 128; r += 256) {
        int valid = (m0 + r < cnt);
        toks[r] = valid ? g_pair_tok[off + m0 + r] : 0;
        wts[r]  = valid ? g_pair_w[off + m0 + r]   : 0.f;
    }
    __syncthreads();

    const int lane = tid & 31, wid = tid >> 5;
    const int gid = lane >> 2, tig = lane & 3;
    const int wm = (wid >> 2) * 64, wn = (wid & 3) * 32;

    const int arow = tid >> 1, aq = (tid & 1) * 16;
    const int asrc = (m0 + arow < cnt) ? (off + m0 + arow) : off;
    const float* aptr = g_h + (size_t)asrc * II + aq;
    const int brow = tid >> 3, bq = (tid & 7) * 16;
    const float* bp = w_down + (size_t)e * II * HH + (size_t)brow * HH + n0 + bq;

    float c[4][4][4];
    #pragma unroll
    for (int i = 0; i < 4; i++)
        #pragma unroll
        for (int j = 0; j < 4; j++)
            #pragma unroll
            for (int q = 0; q < 4; q++) c[i][j][q] = 0.f;

    float4 pa[4], pb[4];
    #pragma unroll
    for (int v = 0; v < 4; v++) {
        pa[v] = *(const float4*)(aptr + v * 4);
        pb[v] = *(const float4*)(bp + v * 4);
    }

    for (int kt = 0; kt < II / 32; kt++) {
        #pragma unroll
        for (int v = 0; v < 4; v++) {
            *(float4*)&As[arow * APAD + aq + v * 4] = tf32r4(pa[v]);
            *(float4*)&Bs[brow * B2PAD + bq + v * 4] = tf32r4(pb[v]);
        }
        __syncthreads();
        if (kt + 1 < II / 32) {
            const int kn = (kt + 1) * 32;
            #pragma unroll
            for (int v = 0; v < 4; v++) {
                pa[v] = *(const float4*)(aptr + kn + v * 4);
                pb[v] = *(const float4*)(bp + (size_t)kn * HH + v * 4);
            }
        }
        #pragma unroll
        for (int ks = 0; ks < 4; ks++) {
            const int kb = ks * 8;
            uint32_t af[4][4], bf[4][2];
            #pragma unroll
            for (int mi = 0; mi < 4; mi++) {
                const int r = wm + mi * 16 + gid;
                af[mi][0] = __float_as_uint(As[r * APAD + kb + tig]);
                af[mi][1] = __float_as_uint(As[(r + 8) * APAD + kb + tig]);
                af[mi][2] = __float_as_uint(As[r * APAD + kb + tig + 4]);
                af[mi][3] = __float_as_uint(As[(r + 8) * APAD + kb + tig + 4]);
            }
            #pragma unroll
            for (int ni = 0; ni < 4; ni++) {
                const int cc = wn + ni * 8 + gid;
                bf[ni][0] = __float_as_uint(Bs[(kb + tig) * B2PAD + cc]);
                bf[ni][1] = __float_as_uint(Bs[(kb + tig + 4) * B2PAD + cc]);
            }
            #pragma unroll
            for (int mi = 0; mi < 4; mi++)
                #pragma unroll
                for (int ni = 0; ni < 4; ni++)
                    mma_t32(c[mi][ni], af[mi], bf[ni]);
        }
        __syncthreads();
    }
    // epilogue: weighted atomicAdd into out
    #pragma unroll
    for (int mi = 0; mi < 4; mi++) {
        #pragma unroll
        for (int half = 0; half < 2; half++) {
            const int ml = wm + mi * 16 + gid + half * 8;
            const int m  = m0 + ml;
            if (m < cnt) {
                const int tok = toks[ml];
                const float w = wts[ml];
                float* dst = out + (size_t)tok * HH + n0 + wn;
                #pragma unroll
                for (int ni = 0; ni < 4; ni++) {
                    atomicAdd(dst + ni * 8 + tig * 2,     w * c[mi][ni][half * 2]);
                    atomicAdd(dst + ni * 8 + tig * 2 + 1, w * c[mi][ni][half * 2 + 1]);
                }
            }
        }
    }
}

// ---------------- launch ----------------
extern "C" void kernel_launch(void* const* d_in, const int* in_sizes, int n_in,
                              void* d_out, int out_size) {
    const float* x      = (const float*)d_in[0];
    const float* gate_w = (const float*)d_in[1];
    const float* w_gate = (const float*)d_in[2];
    const float* w_up   = (const float*)d_in[3];
    const float* w_down = (const float*)d_in[4];
    float* out = (float*)d_out;

    cudaMemsetAsync(d_out, 0, (size_t)out_size * sizeof(float), 0);
    init_kernel<<<1, 32>>>();

    int write_ids = (out_size >= TT * HH + TT * TOPK) ? 1 : 0;
    router_kernel<<<TT, 128>>>(x, gate_w, out, write_ids);
    prefix_kernel<<<1, 32>>>();
    scatter_kernel<<<(TT * TOPK + 255) / 256, 256>>>();

    moe_gemm1<<<dim3(32, II / 64, EE), 256>>>(x, w_gate, w_up);
    moe_gemm2<<<dim3(32, HH / 128, EE), 256>>>(w_down, out);
}

// round 12
// speedup vs baseline: 2.8937x; 1.5067x over previous
#include <cuda_runtime.h>
#include <cstdint>
#include <math.h>

#define TT 4096
#define HH 2048
#define EE 32
#define II 1024
#define TOPK 8
#define MAXPAIRS (TT * TOPK)

// ---------------- device scratch (BSS, allocation-free) ----------------
__device__ int   g_count[EE];
__device__ int   g_cursor[EE];
__device__ int   g_off[EE + 1];
__device__ int   g_topk_e[MAXPAIRS];
__device__ float g_topk_w[MAXPAIRS];
__device__ int   g_pair_tok[MAXPAIRS];
__device__ float g_pair_w[MAXPAIRS];
__device__ int   g_slot[MAXPAIRS];
__device__ float g_xr [(size_t)TT * HH];           // tf32-rounded x
__device__ float g_wgr[(size_t)EE * HH * II];      // tf32-rounded weights
__device__ float g_wur[(size_t)EE * HH * II];
__device__ float g_wdr[(size_t)EE * II * HH];
__device__ float g_h  [(size_t)MAXPAIRS * II];     // intermediate (tf32-rounded)
__device__ float g_y  [(size_t)MAXPAIRS * HH];     // weighted expert outputs

// ---------------- helpers ----------------
__device__ __forceinline__ uint32_t smem_u32(const void* p) {
    uint32_t a;
    asm("{ .reg .u64 t; cvta.to.shared.u64 t, %1; cvt.u32.u64 %0, t; }" : "=r"(a) : "l"(p));
    return a;
}
__device__ __forceinline__ float tf32r(float v) {
    uint32_t u;
    asm("cvt.rna.tf32.f32 %0, %1;" : "=r"(u) : "f"(v));
    return __uint_as_float(u);
}
__device__ __forceinline__ float4 tf32r4(float4 v) {
    v.x = tf32r(v.x); v.y = tf32r(v.y); v.z = tf32r(v.z); v.w = tf32r(v.w);
    return v;
}
__device__ __forceinline__ void mma_t32(float* c, const uint32_t* a, const uint32_t* b) {
    asm volatile(
        "mma.sync.aligned.m16n8k8.row.col.f32.tf32.tf32.f32 "
        "{%0,%1,%2,%3}, {%4,%5,%6,%7}, {%8,%9}, {%0,%1,%2,%3};"
        : "+f"(c[0]), "+f"(c[1]), "+f"(c[2]), "+f"(c[3])
        : "r"(a[0]), "r"(a[1]), "r"(a[2]), "r"(a[3]), "r"(b[0]), "r"(b[1]));
}
__device__ __forceinline__ void cp16(uint32_t dst, const void* src) {
    asm volatile("cp.async.cg.shared.global [%0], [%1], 16;" :: "r"(dst), "l"(src));
}
#define CP_COMMIT() asm volatile("cp.async.commit_group;" ::: "memory")
#define CP_WAIT1()  asm volatile("cp.async.wait_group 1;" ::: "memory")

// ---------------- init ----------------
__global__ void init_kernel() {
    int i = threadIdx.x;
    if (i < EE) { g_count[i] = 0; g_cursor[i] = 0; }
}

// ---------------- round to tf32 (prep) ----------------
__global__ void round_kernel(const float4* __restrict__ src, float4* __restrict__ dst, int n4) {
    int i = blockIdx.x * blockDim.x + threadIdx.x;
    if (i < n4) dst[i] = tf32r4(src[i]);
}

// ---------------- router ----------------
__global__ void router_kernel(const float* __restrict__ x,
                              const float* __restrict__ gate_w,
                              float* __restrict__ out, int write_ids) {
    int t = blockIdx.x;
    int tid = threadIdx.x;           // 128
    int e = tid >> 2, p = tid & 3;
    const float* xr = x + (size_t)t * HH;
    float s = 0.f;
    for (int h = p; h < HH; h += 4)
        s += xr[h] * gate_w[(size_t)h * EE + e];
    __shared__ float part[EE][4];
    part[e][p] = s;
    __syncthreads();
    __shared__ float sc[EE];
    if (tid < EE)
        sc[tid] = part[tid][0] + part[tid][1] + part[tid][2] + part[tid][3];
    __syncthreads();
    if (tid == 0) {
        float mx = sc[0];
        #pragma unroll
        for (int i = 1; i < EE; i++) mx = fmaxf(mx, sc[i]);
        float sum = 0.f;
        for (int i = 0; i < EE; i++) { sc[i] = expf(sc[i] - mx); sum += sc[i]; }
        float inv = 1.f / sum;
        for (int i = 0; i < EE; i++) sc[i] *= inv;
        int ids[TOPK]; float ws[TOPK];
        unsigned used = 0u; float wsum = 0.f;
        for (int k = 0; k < TOPK; k++) {
            int best = 0; float bv = -1.f;
            for (int i = 0; i < EE; i++)
                if (!((used >> i) & 1u) && sc[i] > bv) { bv = sc[i]; best = i; }
            used |= (1u << best); ids[k] = best; ws[k] = bv; wsum += bv;
        }
        float invw = 1.f / wsum;
        for (int k = 0; k < TOPK; k++) {
            g_topk_e[t * TOPK + k] = ids[k];
            g_topk_w[t * TOPK + k] = ws[k] * invw;
            atomicAdd(&g_count[ids[k]], 1);
            if (write_ids)
                out[(size_t)TT * HH + (size_t)t * TOPK + k] = (float)ids[k];
        }
    }
}

__global__ void prefix_kernel() {
    if (threadIdx.x == 0) {
        int acc = 0;
        for (int e = 0; e < EE; e++) { g_off[e] = acc; acc += g_count[e]; }
        g_off[EE] = acc;
    }
}

__global__ void scatter_kernel() {
    int idx = blockIdx.x * blockDim.x + threadIdx.x;
    if (idx >= TT * TOPK) return;
    int e = g_topk_e[idx];
    int pos = atomicAdd(&g_cursor[e], 1);
    int slot = g_off[e] + pos;
    g_pair_tok[slot] = idx / TOPK;
    g_pair_w[slot]   = g_topk_w[idx];
    g_slot[idx]      = slot;
}

// ================= GEMM1: h = silu(X@Wg) * (X@Wu) =================
// BM=128, BN=128, BK=32. 8 warps (2Mx4N), warp tile 64x32 dual (gate+up).
// 3-stage cp.async. smem stage (floats): A 128x36=4608, Bg 32x136=4352, Bu 4352 -> 13312.
#define G1_STAGE_F 13312
#define G1_SMEM (3 * G1_STAGE_F * 4 + 512)
__global__ __launch_bounds__(256, 1) void moe_gemm1() {
    const int e   = blockIdx.z;
    const int cnt = g_count[e];
    const int m0  = blockIdx.x * 128;
    if (m0 >= cnt) return;
    const int n0  = blockIdx.y * 128;
    const int off = g_off[e];

    extern __shared__ float sm[];
    int* toks = (int*)(sm + 3 * G1_STAGE_F);
    const int tid = threadIdx.x;
    for (int r = tid; r < 128; r += 256)
        toks[r] = (m0 + r < cnt) ? g_pair_tok[off + m0 + r] : 0;
    __syncthreads();

    const uint32_t sb = smem_u32(sm);
    // A fill mapping: 1024 chunks of 16B; this thread: rows ar+32j, col chunk (tid&7)
    const int ar = tid >> 3, ac = (tid & 7);
    const float* aptr[4];
    #pragma unroll
    for (int j = 0; j < 4; j++)
        aptr[j] = g_xr + (size_t)toks[ar + 32 * j] * HH + ac * 4;
    // B fill mapping: rows br+8j, col chunk (tid&31)
    const int br = tid >> 5, bc = (tid & 31);
    const float* gbase = g_wgr + (size_t)e * HH * II + n0 + bc * 4;
    const float* ubase = g_wur + (size_t)e * HH * II + n0 + bc * 4;

    const int lane = tid & 31, wid = tid >> 5;
    const int gid = lane >> 2, tig = lane & 3;
    const int wm = (wid >> 2) * 64, wn = (wid & 3) * 32;

    float cg[4][4][4], cu[4][4][4];
    #pragma unroll
    for (int i = 0; i < 4; i++)
        #pragma unroll
        for (int j = 0; j < 4; j++)
            #pragma unroll
            for (int q = 0; q < 4; q++) { cg[i][j][q] = 0.f; cu[i][j][q] = 0.f; }

    const int KT = HH / 32;
    #pragma unroll 1
    for (int kt = -2; kt < KT; kt++) {
        // fill stage for tile kt+2
        const int ft = kt + 2;
        if (ft < KT) {
            const int s = ft % 3;
            const int k0 = ft * 32;
            const uint32_t a_s = sb + s * (G1_STAGE_F * 4);
            #pragma unroll
            for (int j = 0; j < 4; j++)
                cp16(a_s + (ar + 32 * j) * 144 + ac * 16, aptr[j] + k0);
            const uint32_t g_s = a_s + 4608 * 4;
            const uint32_t u_s = g_s + 4352 * 4;
            #pragma unroll
            for (int j = 0; j < 4; j++) {
                cp16(g_s + (br + 8 * j) * 544 + bc * 16, gbase + (size_t)(k0 + br + 8 * j) * II);
                cp16(u_s + (br + 8 * j) * 544 + bc * 16, ubase + (size_t)(k0 + br + 8 * j) * II);
            }
        }
        CP_COMMIT();
        if (kt < 0) continue;
        CP_WAIT1();
        __syncthreads();
        // compute tile kt
        const float* A = sm + (kt % 3) * G1_STAGE_F;
        const float* G = A + 4608;
        const float* U = G + 4352;
        #pragma unroll
        for (int ks = 0; ks < 4; ks++) {
            const int kb = ks * 8;
            uint32_t af[4][4], bg[4][2], bu[4][2];
            #pragma unroll
            for (int mi = 0; mi < 4; mi++) {
                const int r = wm + mi * 16 + gid;
                af[mi][0] = __float_as_uint(A[r * 36 + kb + tig]);
                af[mi][1] = __float_as_uint(A[(r + 8) * 36 + kb + tig]);
                af[mi][2] = __float_as_uint(A[r * 36 + kb + tig + 4]);
                af[mi][3] = __float_as_uint(A[(r + 8) * 36 + kb + tig + 4]);
            }
            #pragma unroll
            for (int ni = 0; ni < 4; ni++) {
                const int c = wn + ni * 8 + gid;
                bg[ni][0] = __float_as_uint(G[(kb + tig) * 136 + c]);
                bg[ni][1] = __float_as_uint(G[(kb + tig + 4) * 136 + c]);
                bu[ni][0] = __float_as_uint(U[(kb + tig) * 136 + c]);
                bu[ni][1] = __float_as_uint(U[(kb + tig + 4) * 136 + c]);
            }
            #pragma unroll
            for (int mi = 0; mi < 4; mi++)
                #pragma unroll
                for (int ni = 0; ni < 4; ni++) {
                    mma_t32(cg[mi][ni], af[mi], bg[ni]);
                    mma_t32(cu[mi][ni], af[mi], bu[ni]);
                }
        }
        __syncthreads();
    }
    // epilogue: silu(g)*u, tf32-round, store
    #pragma unroll
    for (int mi = 0; mi < 4; mi++) {
        #pragma unroll
        for (int half = 0; half < 2; half++) {
            const int m = m0 + wm + mi * 16 + gid + half * 8;
            if (m < cnt) {
                float* hrow = g_h + (size_t)(off + m) * II + n0 + wn;
                #pragma unroll
                for (int ni = 0; ni < 4; ni++) {
                    float g0 = cg[mi][ni][half * 2], g1 = cg[mi][ni][half * 2 + 1];
                    float u0 = cu[mi][ni][half * 2], u1 = cu[mi][ni][half * 2 + 1];
                    float2 o;
                    o.x = tf32r(g0 / (1.f + __expf(-g0)) * u0);
                    o.y = tf32r(g1 / (1.f + __expf(-g1)) * u1);
                    *(float2*)(hrow + ni * 8 + tig * 2) = o;
                }
            }
        }
    }
}

// ================= GEMM2: y[slot] = w * (h @ Wd) =================
// BM=128, BN=256, BK=32. 8 warps (2Mx4N), warp tile 64x64.
// smem stage (floats): A 128x36=4608, B 32x264=8448 -> 13056.
#define G2_STAGE_F 13056
#define G2_SMEM (3 * G2_STAGE_F * 4 + 512)
__global__ __launch_bounds__(256, 1) void moe_gemm2() {
    const int e   = blockIdx.z;
    const int cnt = g_count[e];
    const int m0  = blockIdx.x * 128;
    if (m0 >= cnt) return;
    const int n0  = blockIdx.y * 256;
    const int off = g_off[e];

    extern __shared__ float sm[];
    float* wts = sm + 3 * G2_STAGE_F;
    const int tid = threadIdx.x;
    for (int r = tid; r < 128; r += 256)
        wts[r] = (m0 + r < cnt) ? g_pair_w[off + m0 + r] : 0.f;
    __syncthreads();

    const uint32_t sb = smem_u32(sm);
    const int ar = tid >> 3, ac = (tid & 7);
    const float* aptr[4];
    #pragma unroll
    for (int j = 0; j < 4; j++) {
        int row = m0 + ar + 32 * j;
        int slot = (row < cnt) ? (off + row) : off;
        aptr[j] = g_h + (size_t)slot * II + ac * 4;
    }
    // B fill: 2048 chunks; thread: rows (tid>>6)+4j (j<8), col chunk (tid&63)
    const int br = tid >> 6, bc = (tid & 63);
    const float* bbase = g_wdr + (size_t)e * II * HH + n0 + bc * 4;

    const int lane = tid & 31, wid = tid >> 5;
    const int gid = lane >> 2, tig = lane & 3;
    const int wm = (wid >> 2) * 64, wn = (wid & 3) * 64;

    float c[4][8][4];
    #pragma unroll
    for (int i = 0; i < 4; i++)
        #pragma unroll
        for (int j = 0; j < 8; j++)
            #pragma unroll
            for (int q = 0; q < 4; q++) c[i][j][q] = 0.f;

    const int KT = II / 32;
    #pragma unroll 1
    for (int kt = -2; kt < KT; kt++) {
        const int ft = kt + 2;
        if (ft < KT) {
            const int s = ft % 3;
            const int k0 = ft * 32;
            const uint32_t a_s = sb + s * (G2_STAGE_F * 4);
            #pragma unroll
            for (int j = 0; j < 4; j++)
                cp16(a_s + (ar + 32 * j) * 144 + ac * 16, aptr[j] + k0);
            const uint32_t b_s = a_s + 4608 * 4;
            #pragma unroll
            for (int j = 0; j < 8; j++)
                cp16(b_s + (br + 4 * j) * 1056 + bc * 16, bbase + (size_t)(k0 + br + 4 * j) * HH);
        }
        CP_COMMIT();
        if (kt < 0) continue;
        CP_WAIT1();
        __syncthreads();
        const float* A = sm + (kt % 3) * G2_STAGE_F;
        const float* B = A + 4608;
        #pragma unroll
        for (int ks = 0; ks < 4; ks++) {
            const int kb = ks * 8;
            uint32_t af[4][4], bf[8][2];
            #pragma unroll
            for (int mi = 0; mi < 4; mi++) {
                const int r = wm + mi * 16 + gid;
                af[mi][0] = __float_as_uint(A[r * 36 + kb + tig]);
                af[mi][1] = __float_as_uint(A[(r + 8) * 36 + kb + tig]);
                af[mi][2] = __float_as_uint(A[r * 36 + kb + tig + 4]);
                af[mi][3] = __float_as_uint(A[(r + 8) * 36 + kb + tig + 4]);
            }
            #pragma unroll
            for (int ni = 0; ni < 8; ni++) {
                const int cc = wn + ni * 8 + gid;
                bf[ni][0] = __float_as_uint(B[(kb + tig) * 264 + cc]);
                bf[ni][1] = __float_as_uint(B[(kb + tig + 4) * 264 + cc]);
            }
            #pragma unroll
            for (int mi = 0; mi < 4; mi++)
                #pragma unroll
                for (int ni = 0; ni < 8; ni++)
                    mma_t32(c[mi][ni], af[mi], bf[ni]);
        }
        __syncthreads();
    }
    // epilogue: weighted store into g_y
    #pragma unroll
    for (int mi = 0; mi < 4; mi++) {
        #pragma unroll
        for (int half = 0; half < 2; half++) {
            const int ml = wm + mi * 16 + gid + half * 8;
            const int m  = m0 + ml;
            if (m < cnt) {
                const float w = wts[ml];
                float* yrow = g_y + (size_t)(off + m) * HH + n0 + wn;
                #pragma unroll
                for (int ni = 0; ni < 8; ni++) {
                    float2 o;
                    o.x = w * c[mi][ni][half * 2];
                    o.y = w * c[mi][ni][half * 2 + 1];
                    *(float2*)(yrow + ni * 8 + tig * 2) = o;
                }
            }
        }
    }
}

// ---------------- combine: out[t] = sum_k g_y[slot(t,k)] ----------------
__global__ void combine_kernel(float* __restrict__ out) {
    const int t = blockIdx.x;
    const int tid = threadIdx.x;   // 256
    __shared__ int s8[TOPK];
    if (tid < TOPK) s8[tid] = g_slot[t * TOPK + tid];
    __syncthreads();
    #pragma unroll
    for (int rep = 0; rep < 2; rep++) {
        const int cc = (tid + rep * 256) * 4;
        float4 acc = make_float4(0.f, 0.f, 0.f, 0.f);
        #pragma unroll
        for (int k = 0; k < TOPK; k++) {
            const float4 v = *(const float4*)(g_y + (size_t)s8[k] * HH + cc);
            acc.x += v.x; acc.y += v.y; acc.z += v.z; acc.w += v.w;
        }
        *(float4*)(out + (size_t)t * HH + cc) = acc;
    }
}

// ---------------- launch ----------------
extern "C" void kernel_launch(void* const* d_in, const int* in_sizes, int n_in,
                              void* d_out, int out_size) {
    const float* x      = (const float*)d_in[0];
    const float* gate_w = (const float*)d_in[1];
    const float* w_gate = (const float*)d_in[2];
    const float* w_up   = (const float*)d_in[3];
    const float* w_down = (const float*)d_in[4];
    float* out = (float*)d_out;

    cudaFuncSetAttribute((const void*)moe_gemm1,
                         cudaFuncAttributeMaxDynamicSharedMemorySize, G1_SMEM);
    cudaFuncSetAttribute((const void*)moe_gemm2,
                         cudaFuncAttributeMaxDynamicSharedMemorySize, G2_SMEM);

    init_kernel<<<1, 32>>>();

    int write_ids = (out_size >= TT * HH + TT * TOPK) ? 1 : 0;
    router_kernel<<<TT, 128>>>(x, gate_w, out, write_ids);
    prefix_kernel<<<1, 32>>>();
    scatter_kernel<<<(TT * TOPK + 255) / 256, 256>>>();

    // tf32 pre-rounding
    {
        float* xr  = nullptr; float* wg = nullptr; float* wu = nullptr; float* wd = nullptr;
        cudaGetSymbolAddress((void**)&xr, g_xr);
        cudaGetSymbolAddress((void**)&wg, g_wgr);
        cudaGetSymbolAddress((void**)&wu, g_wur);
        cudaGetSymbolAddress((void**)&wd, g_wdr);
        int nx = TT * HH / 4;
        int nw = (int)((size_t)EE * HH * II / 4);
        round_kernel<<<(nx + 255) / 256, 256>>>((const float4*)x,      (float4*)xr, nx);
        round_kernel<<<(nw + 255) / 256, 256>>>((const float4*)w_gate, (float4*)wg, nw);
        round_kernel<<<(nw + 255) / 256, 256>>>((const float4*)w_up,   (float4*)wu, nw);
        round_kernel<<<(nw + 255) / 256, 256>>>((const float4*)w_down, (float4*)wd, nw);
    }

    moe_gemm1<<<dim3(32, II / 128, EE), 256, G1_SMEM>>>();
    moe_gemm2<<<dim3(32, HH / 256, EE), 256, G2_SMEM>>>();
    combine_kernel<<<TT, 256>>>(out);
}